// round 13
// baseline (speedup 1.0000x reference)
#include <cuda_runtime.h>
#include <cuda_fp16.h>

#define N_NODES 100000
#define N_EDGES 1600000
#define NFEAT   128
#define NHID    64
#define CAP     64          // padded bucket capacity per row (max degree ~45)

// ---- scratch (__device__ globals: no runtime allocation) -------------------
__device__ __half             g_support[N_NODES * NHID];     // 12.8 MB (fp16)
__device__ int                g_cnt[N_NODES];                 // insertion cursor == degree
__device__ unsigned long long g_edges[N_NODES * CAP];         // 51.2 MB padded buckets

// ---------------------------------------------------------------------------
// JAX partitionable threefry2x32, key (0,42), count (0, i): returns out0^out1
// ---------------------------------------------------------------------------
__device__ __forceinline__ unsigned tf_hash(unsigned i) {
    const unsigned ks0 = 0u, ks1 = 42u, ks2 = 0x1BD11BF0u;  // 0 ^ 42 ^ 0x1BD11BDA
    unsigned x0 = ks0;        // counts_hi = 0
    unsigned x1 = i + ks1;    // counts_lo = i
#define TFR(r) { x0 += x1; x1 = __funnelshift_l(x1, x1, (r)); x1 ^= x0; }
    TFR(13) TFR(15) TFR(26) TFR(6)   x0 += ks1; x1 += ks2 + 1u;
    TFR(17) TFR(29) TFR(16) TFR(24)  x0 += ks2; x1 += ks0 + 2u;
    TFR(13) TFR(15) TFR(26) TFR(6)   x0 += ks0; x1 += ks1 + 3u;
    TFR(17) TFR(29) TFR(16) TFR(24)  x0 += ks1; x1 += ks2 + 4u;
    TFR(13) TFR(15) TFR(26) TFR(6)   x0 += ks2; x1 += ks0 + 5u;
#undef TFR
    return x0 ^ x1;
}

// ---------------------------------------------------------------------------
// Bucket build (R11/R12 version): four edges per thread, vectorized loads.
// ---------------------------------------------------------------------------
__global__ __launch_bounds__(256) void build_kernel(const int*   __restrict__ erow,
                                                    const int*   __restrict__ ecol,
                                                    const float* __restrict__ ev) {
    int base = (blockIdx.x * 256 + threadIdx.x) * 4;
    if (base >= N_EDGES) return;   // N_EDGES % 4 == 0: active threads fully in-bounds
    int4   r4 = *reinterpret_cast<const int4*>(erow + base);
    int4   c4 = *reinterpret_cast<const int4*>(ecol + base);
    float4 v4 = *reinterpret_cast<const float4*>(ev + base);

    int p0 = atomicAdd(&g_cnt[r4.x], 1);
    int p1 = atomicAdd(&g_cnt[r4.y], 1);
    int p2 = atomicAdd(&g_cnt[r4.z], 1);
    int p3 = atomicAdd(&g_cnt[r4.w], 1);

    if (p0 < CAP)
        g_edges[r4.x * CAP + p0] =
            ((unsigned long long)__float_as_uint(v4.x) << 32) | (unsigned)c4.x;
    if (p1 < CAP)
        g_edges[r4.y * CAP + p1] =
            ((unsigned long long)__float_as_uint(v4.y) << 32) | (unsigned)c4.y;
    if (p2 < CAP)
        g_edges[r4.z * CAP + p2] =
            ((unsigned long long)__float_as_uint(v4.z) << 32) | (unsigned)c4.z;
    if (p3 < CAP)
        g_edges[r4.w * CAP + p3] =
            ((unsigned long long)__float_as_uint(v4.w) << 32) | (unsigned)c4.w;
}

// ---------------------------------------------------------------------------
// GEMM: support[100000,64] = x[100000,128] @ W[128,64]; fp32 math, fp16 store.
// ---------------------------------------------------------------------------
__global__ __launch_bounds__(256, 2) void gemm_kernel(const float* __restrict__ x,
                                                      const float* __restrict__ W) {
    __shared__ float Xs[256][33];
    __shared__ float Ws[32][64];
    const int tid  = threadIdx.x;
    const int lane = tid & 31;
    const int tx   = tid >> 5;
    const int bm   = blockIdx.x * 256;

    float acc[8][8];
#pragma unroll
    for (int j = 0; j < 8; j++)
#pragma unroll
        for (int n = 0; n < 8; n++) acc[j][n] = 0.f;

    for (int kc = 0; kc < 4; kc++) {
#pragma unroll
        for (int i = 0; i < 8; i++) {
            int fi  = tid + i * 256;
            int row = fi >> 3;
            int kq  = fi & 7;
            int grow = bm + row;
            float4 v = make_float4(0.f, 0.f, 0.f, 0.f);
            if (grow < N_NODES)
                v = reinterpret_cast<const float4*>(x)[grow * 32 + kc * 8 + kq];
            Xs[row][kq * 4 + 0] = v.x;
            Xs[row][kq * 4 + 1] = v.y;
            Xs[row][kq * 4 + 2] = v.z;
            Xs[row][kq * 4 + 3] = v.w;
        }
#pragma unroll
        for (int i = 0; i < 2; i++) {
            int fi = tid + i * 256;
            int kk = fi >> 4;
            int nq = fi & 15;
            reinterpret_cast<float4*>(&Ws[kk][nq * 4])[0] =
                reinterpret_cast<const float4*>(W)[(kc * 32 + kk) * 16 + nq];
        }
        __syncthreads();

#pragma unroll 4
        for (int k = 0; k < 32; k++) {
            float4 b0 = *reinterpret_cast<const float4*>(&Ws[k][tx * 8]);
            float4 b1 = *reinterpret_cast<const float4*>(&Ws[k][tx * 8 + 4]);
#pragma unroll
            for (int j = 0; j < 8; j++) {
                float a = Xs[lane + 32 * j][k];
                acc[j][0] += a * b0.x; acc[j][1] += a * b0.y;
                acc[j][2] += a * b0.z; acc[j][3] += a * b0.w;
                acc[j][4] += a * b1.x; acc[j][5] += a * b1.y;
                acc[j][6] += a * b1.z; acc[j][7] += a * b1.w;
            }
        }
        __syncthreads();
    }

#pragma unroll
    for (int j = 0; j < 8; j++) {
        int r = bm + lane + 32 * j;
        if (r < N_NODES) {
            __half2 h[4];
#pragma unroll
            for (int q = 0; q < 4; q++)
                h[q] = __floats2half2_rn(acc[j][2 * q], acc[j][2 * q + 1]);
            reinterpret_cast<uint4*>(&g_support[r * 64 + tx * 8])[0] =
                *reinterpret_cast<uint4*>(h);
        }
    }
}

// ---------------------------------------------------------------------------
// Dummy no-op kernel: shifts ncu's skip-5 capture window onto reduce_kernel.
// ---------------------------------------------------------------------------
__global__ void dummy_kernel() {}

// ---------------------------------------------------------------------------
// Gather-reduce + fused epilogue (proven shape): one warp per row.
// Delta vs R12: edge-word load masked by lane < nb (dead slots not fetched).
// ---------------------------------------------------------------------------
__global__ __launch_bounds__(256) void reduce_kernel(float* __restrict__ out,
                                                     const float* __restrict__ bias) {
    int lane = threadIdx.x & 31;
    int wid  = threadIdx.x >> 5;
    int row  = blockIdx.x * 8 + wid;          // grid 12500 -> exact

    int deg = g_cnt[row];
    if (deg > CAP) deg = CAP;
    const unsigned long long* ebase = g_edges + (size_t)row * CAP;

    const __half2* sup = reinterpret_cast<const __half2*>(g_support);
    float ax = 0.f, ay = 0.f;

    int nb = deg < 32 ? deg : 32;
    unsigned long long ew_l = 0;
    if (lane < nb) ew_l = ebase[lane];        // fetch only live slots
#pragma unroll 4
    for (int j = 0; j < nb; j++) {
        unsigned long long ew = __shfl_sync(0xFFFFFFFFu, ew_l, j);
        unsigned c = (unsigned)ew;
        float    v = __uint_as_float((unsigned)(ew >> 32));
        float2 s = __half22float2(sup[c * 32u + lane]);
        ax += v * s.x;
        ay += v * s.y;
    }
    if (deg > 32) {   // rare tail (P ~ 1e-4 of rows)
        int nb2 = deg - 32;
        unsigned long long ew_h = 0;
        if (lane < nb2) ew_h = ebase[32 + lane];
#pragma unroll 4
        for (int j = 0; j < nb2; j++) {
            unsigned long long ew = __shfl_sync(0xFFFFFFFFu, ew_h, j);
            unsigned c = (unsigned)ew;
            float    v = __uint_as_float((unsigned)(ew >> 32));
            float2 s = __half22float2(sup[c * 32u + lane]);
            ax += v * s.x;
            ay += v * s.y;
        }
    }

    float2 bv = reinterpret_cast<const float2*>(bias)[lane];
    float h0 = ax + bv.x, h1 = ay + bv.y;
    h0 = h0 > 0.f ? 2.f * h0 : 0.f;
    h1 = h1 > 0.f ? 2.f * h1 : 0.f;

    unsigned i0 = (unsigned)row * 64u + (unsigned)lane * 2u;
    unsigned m0 = tf_hash(i0);
    unsigned m1 = tf_hash(i0 + 1u);

    float2 o;
    o.x = (m0 & 0x80000000u) ? 0.f : h0;
    o.y = (m1 & 0x80000000u) ? 0.f : h1;
    reinterpret_cast<float2*>(out)[(unsigned)row * 32u + lane] = o;
}

// ---------------------------------------------------------------------------
extern "C" void kernel_launch(void* const* d_in, const int* in_sizes, int n_in,
                              void* d_out, int out_size) {
    const float* x    = (const float*)d_in[0];
    const int*   erow = (const int*)  d_in[1];
    const int*   ecol = (const int*)  d_in[2];
    const float* ev   = (const float*)d_in[3];
    const float* W    = (const float*)d_in[4];
    const float* b    = (const float*)d_in[5];
    float* out = (float*)d_out;

    void* cnt_ptr = nullptr;
    cudaGetSymbolAddress(&cnt_ptr, g_cnt);
    cudaMemsetAsync(cnt_ptr, 0, N_NODES * sizeof(int), 0);

    build_kernel<<<1563, 256>>>(erow, ecol, ev);   // 400128 threads * 4 edges
    gemm_kernel <<<391, 256>>>(x, W);
    // 6 launches/replay puts ncu's skip-5 capture on reduce_kernel
    dummy_kernel<<<1, 32>>>();
    dummy_kernel<<<1, 32>>>();
    reduce_kernel<<<12500, 256>>>(out, b);
}

// round 14
// speedup vs baseline: 1.0986x; 1.0986x over previous
#include <cuda_runtime.h>
#include <cuda_fp16.h>

#define N_NODES 100000
#define N_EDGES 1600000
#define NFEAT   128
#define NHID    64
#define CAP     64          // padded bucket capacity per row (max degree ~45)

// ---- scratch (__device__ globals: no runtime allocation) -------------------
__device__ __half             g_support[N_NODES * NHID];     // 12.8 MB (fp16)
__device__ int                g_cnt[N_NODES];                 // insertion cursor == degree
__device__ unsigned long long g_edges[N_NODES * CAP];         // 51.2 MB padded buckets
__device__ unsigned short     g_mask[N_NODES * 4];            // 800 KB dropout keep-bits

// ---------------------------------------------------------------------------
// JAX partitionable threefry2x32, key (0,42), count (0, i): returns out0^out1
// ---------------------------------------------------------------------------
__device__ __forceinline__ unsigned tf_hash(unsigned i) {
    const unsigned ks0 = 0u, ks1 = 42u, ks2 = 0x1BD11BF0u;  // 0 ^ 42 ^ 0x1BD11BDA
    unsigned x0 = ks0;        // counts_hi = 0
    unsigned x1 = i + ks1;    // counts_lo = i
#define TFR(r) { x0 += x1; x1 = __funnelshift_l(x1, x1, (r)); x1 ^= x0; }
    TFR(13) TFR(15) TFR(26) TFR(6)   x0 += ks1; x1 += ks2 + 1u;
    TFR(17) TFR(29) TFR(16) TFR(24)  x0 += ks2; x1 += ks0 + 2u;
    TFR(13) TFR(15) TFR(26) TFR(6)   x0 += ks0; x1 += ks1 + 3u;
    TFR(17) TFR(29) TFR(16) TFR(24)  x0 += ks1; x1 += ks2 + 4u;
    TFR(13) TFR(15) TFR(26) TFR(6)   x0 += ks2; x1 += ks0 + 5u;
#undef TFR
    return x0 ^ x1;
}

// ---------------------------------------------------------------------------
// Bucket build + dropout-mask generation.
// Edges: four per thread, vectorized loads (R11-proven).
// Masks: thread t computes 16 threefry hashes for elements
//        (t>>2)*64 + (t&3)*16 + [0..16) and stores a 16-bit keep-mask.
// The ~1K ALU instrs/thread hide in build's 97%-idle issue slots.
// ---------------------------------------------------------------------------
__global__ __launch_bounds__(256) void build_kernel(const int*   __restrict__ erow,
                                                    const int*   __restrict__ ecol,
                                                    const float* __restrict__ ev) {
    int t = blockIdx.x * 256 + threadIdx.x;
    int base = t * 4;
    if (base >= N_EDGES) return;   // N_EDGES % 4 == 0: active threads fully in-bounds
    int4   r4 = *reinterpret_cast<const int4*>(erow + base);
    int4   c4 = *reinterpret_cast<const int4*>(ecol + base);
    float4 v4 = *reinterpret_cast<const float4*>(ev + base);

    // ---- dropout mask quarter-word (ALU; overlaps the loads above) ----
    {
        unsigned ebase = (unsigned)t * 16u;   // == (t>>2)*64 + (t&3)*16
        unsigned m = 0;
#pragma unroll 4
        for (int k = 0; k < 16; k++)
            m |= ((~tf_hash(ebase + k)) >> 31) << k;   // keep=1 iff bit31==0
        g_mask[t] = (unsigned short)m;
    }

    int p0 = atomicAdd(&g_cnt[r4.x], 1);
    int p1 = atomicAdd(&g_cnt[r4.y], 1);
    int p2 = atomicAdd(&g_cnt[r4.z], 1);
    int p3 = atomicAdd(&g_cnt[r4.w], 1);

    if (p0 < CAP)
        g_edges[r4.x * CAP + p0] =
            ((unsigned long long)__float_as_uint(v4.x) << 32) | (unsigned)c4.x;
    if (p1 < CAP)
        g_edges[r4.y * CAP + p1] =
            ((unsigned long long)__float_as_uint(v4.y) << 32) | (unsigned)c4.y;
    if (p2 < CAP)
        g_edges[r4.z * CAP + p2] =
            ((unsigned long long)__float_as_uint(v4.z) << 32) | (unsigned)c4.z;
    if (p3 < CAP)
        g_edges[r4.w * CAP + p3] =
            ((unsigned long long)__float_as_uint(v4.w) << 32) | (unsigned)c4.w;
}

// ---------------------------------------------------------------------------
// GEMM: support[100000,64] = x[100000,128] @ W[128,64]; fp32 math, fp16 store.
// ---------------------------------------------------------------------------
__global__ __launch_bounds__(256, 2) void gemm_kernel(const float* __restrict__ x,
                                                      const float* __restrict__ W) {
    __shared__ float Xs[256][33];
    __shared__ float Ws[32][64];
    const int tid  = threadIdx.x;
    const int lane = tid & 31;
    const int tx   = tid >> 5;
    const int bm   = blockIdx.x * 256;

    float acc[8][8];
#pragma unroll
    for (int j = 0; j < 8; j++)
#pragma unroll
        for (int n = 0; n < 8; n++) acc[j][n] = 0.f;

    for (int kc = 0; kc < 4; kc++) {
#pragma unroll
        for (int i = 0; i < 8; i++) {
            int fi  = tid + i * 256;
            int row = fi >> 3;
            int kq  = fi & 7;
            int grow = bm + row;
            float4 v = make_float4(0.f, 0.f, 0.f, 0.f);
            if (grow < N_NODES)
                v = reinterpret_cast<const float4*>(x)[grow * 32 + kc * 8 + kq];
            Xs[row][kq * 4 + 0] = v.x;
            Xs[row][kq * 4 + 1] = v.y;
            Xs[row][kq * 4 + 2] = v.z;
            Xs[row][kq * 4 + 3] = v.w;
        }
#pragma unroll
        for (int i = 0; i < 2; i++) {
            int fi = tid + i * 256;
            int kk = fi >> 4;
            int nq = fi & 15;
            reinterpret_cast<float4*>(&Ws[kk][nq * 4])[0] =
                reinterpret_cast<const float4*>(W)[(kc * 32 + kk) * 16 + nq];
        }
        __syncthreads();

#pragma unroll 4
        for (int k = 0; k < 32; k++) {
            float4 b0 = *reinterpret_cast<const float4*>(&Ws[k][tx * 8]);
            float4 b1 = *reinterpret_cast<const float4*>(&Ws[k][tx * 8 + 4]);
#pragma unroll
            for (int j = 0; j < 8; j++) {
                float a = Xs[lane + 32 * j][k];
                acc[j][0] += a * b0.x; acc[j][1] += a * b0.y;
                acc[j][2] += a * b0.z; acc[j][3] += a * b0.w;
                acc[j][4] += a * b1.x; acc[j][5] += a * b1.y;
                acc[j][6] += a * b1.z; acc[j][7] += a * b1.w;
            }
        }
        __syncthreads();
    }

#pragma unroll
    for (int j = 0; j < 8; j++) {
        int r = bm + lane + 32 * j;
        if (r < N_NODES) {
            __half2 h[4];
#pragma unroll
            for (int q = 0; q < 4; q++)
                h[q] = __floats2half2_rn(acc[j][2 * q], acc[j][2 * q + 1]);
            reinterpret_cast<uint4*>(&g_support[r * 64 + tx * 8])[0] =
                *reinterpret_cast<uint4*>(h);
        }
    }
}

// ---------------------------------------------------------------------------
// Gather-reduce + fused epilogue (proven shape): one warp per row.
// Dropout mask now read as one warp-uniform 8B word (bit f = keep elem f).
// ---------------------------------------------------------------------------
__global__ __launch_bounds__(256) void reduce_kernel(float* __restrict__ out,
                                                     const float* __restrict__ bias) {
    int lane = threadIdx.x & 31;
    int wid  = threadIdx.x >> 5;
    int row  = blockIdx.x * 8 + wid;          // grid 12500 -> exact

    int deg = g_cnt[row];
    if (deg > CAP) deg = CAP;
    const unsigned long long* ebase = g_edges + (size_t)row * CAP;

    // warp-uniform 64-bit keep-mask for this row (broadcast load)
    unsigned long long mword =
        reinterpret_cast<const unsigned long long*>(g_mask)[row];

    const __half2* sup = reinterpret_cast<const __half2*>(g_support);
    float ax = 0.f, ay = 0.f;

    int nb = deg < 32 ? deg : 32;
    unsigned long long ew_l = 0;
    if (lane < nb) ew_l = ebase[lane];        // fetch only live slots
#pragma unroll 4
    for (int j = 0; j < nb; j++) {
        unsigned long long ew = __shfl_sync(0xFFFFFFFFu, ew_l, j);
        unsigned c = (unsigned)ew;
        float    v = __uint_as_float((unsigned)(ew >> 32));
        float2 s = __half22float2(sup[c * 32u + lane]);
        ax += v * s.x;
        ay += v * s.y;
    }
    if (deg > 32) {   // rare tail (P ~ 1e-4 of rows)
        int nb2 = deg - 32;
        unsigned long long ew_h = 0;
        if (lane < nb2) ew_h = ebase[32 + lane];
#pragma unroll 4
        for (int j = 0; j < nb2; j++) {
            unsigned long long ew = __shfl_sync(0xFFFFFFFFu, ew_h, j);
            unsigned c = (unsigned)ew;
            float    v = __uint_as_float((unsigned)(ew >> 32));
            float2 s = __half22float2(sup[c * 32u + lane]);
            ax += v * s.x;
            ay += v * s.y;
        }
    }

    float2 bv = reinterpret_cast<const float2*>(bias)[lane];
    float h0 = ax + bv.x, h1 = ay + bv.y;
    h0 = h0 > 0.f ? 2.f * h0 : 0.f;
    h1 = h1 > 0.f ? 2.f * h1 : 0.f;

    float2 o;
    o.x = ((mword >> (2 * lane))     & 1ull) ? h0 : 0.f;
    o.y = ((mword >> (2 * lane + 1)) & 1ull) ? h1 : 0.f;
    reinterpret_cast<float2*>(out)[(unsigned)row * 32u + lane] = o;
}

// ---------------------------------------------------------------------------
extern "C" void kernel_launch(void* const* d_in, const int* in_sizes, int n_in,
                              void* d_out, int out_size) {
    const float* x    = (const float*)d_in[0];
    const int*   erow = (const int*)  d_in[1];
    const int*   ecol = (const int*)  d_in[2];
    const float* ev   = (const float*)d_in[3];
    const float* W    = (const float*)d_in[4];
    const float* b    = (const float*)d_in[5];
    float* out = (float*)d_out;

    void* cnt_ptr = nullptr;
    cudaGetSymbolAddress(&cnt_ptr, g_cnt);
    cudaMemsetAsync(cnt_ptr, 0, N_NODES * sizeof(int), 0);

    build_kernel<<<1563, 256>>>(erow, ecol, ev);   // 400128 threads: 4 edges + 16 mask bits each
    gemm_kernel <<<391, 256>>>(x, W);
    reduce_kernel<<<12500, 256>>>(out, b);
}